// round 1
// baseline (speedup 1.0000x reference)
#include <cuda_runtime.h>
#include <cstdint>

// Beam hypotheses update.
// Per row b:
//   score = slp[b]/cur_len ; cond = (len<8)|(score>worst)
//   insert score at idx = (len+1>9 ? 0 : 8), stable-argsort 9 scores,
//   permute board + items rows accordingly (items row idx gets hyp[:cur_len] overlay),
//   worst' = (len+1>8 ? sorted[1] : min(worst,score)).
// Output (float32, concatenated): len[B], worst[B], board[B,9], items[B,9,G].

#define NSLOT 9

__global__ __launch_bounds__(128) void beam_update_kernel(
    const int*   __restrict__ hyp,        // [B, hyp_w]
    const float* __restrict__ slp,        // [B]
    const int*   __restrict__ lnst,       // [B]
    const float* __restrict__ worst_in,   // [B]
    const float* __restrict__ board_in,   // [B, 9]
    const int*   __restrict__ items_in,   // [B, 9, G]
    const int*   __restrict__ curlen_ptr, // scalar (may be null)
    float*       __restrict__ out,
    int batch, int hyp_w, int gen_len)
{
    const int j   = blockIdx.x;          // output slot 0..8
    const int b   = blockIdx.y;          // batch row
    const int tid = threadIdx.x;

    const int cur_len   = curlen_ptr ? __ldg(curlen_ptr) : hyp_w;
    const int num_beams = NSLOT - 1;

    // ---- per-row metadata (computed redundantly by every thread; uniform) ----
    const float score = __ldg(&slp[b]) / (float)cur_len;   // length_penalty = 1.0
    const int   ln    = __ldg(&lnst[b]);
    const float worst = __ldg(&worst_in[b]);
    const bool  cond  = (ln < num_beams) || (score > worst);
    const int   new_len = ln + 1;
    const int   ins_idx = (new_len > NSLOT) ? 0 : num_beams;

    float bv[NSLOT];
    int   oi[NSLOT];
#pragma unroll
    for (int i = 0; i < NSLOT; i++) {
        bv[i] = __ldg(&board_in[(size_t)b * NSLOT + i]);
        oi[i] = i;
    }
#pragma unroll
    for (int i = 0; i < NSLOT; i++)
        if (i == ins_idx) bv[i] = score;   // predicated, register-resident

    // Fully unrolled bubble sort on (value, original-index); strict key order
    // == stable argsort result (ties broken by original index).
#pragma unroll
    for (int p = 0; p < NSLOT - 1; p++) {
#pragma unroll
        for (int k = 0; k < NSLOT - 1; k++) {
            if (k < NSLOT - 1 - p) {
                bool sw = (bv[k] > bv[k + 1]) ||
                          (bv[k] == bv[k + 1] && oi[k] > oi[k + 1]);
                if (sw) {
                    float tv = bv[k]; bv[k] = bv[k + 1]; bv[k + 1] = tv;
                    int   ti = oi[k]; oi[k] = oi[k + 1]; oi[k + 1] = ti;
                }
            }
        }
    }

    const float new_worst = (new_len > num_beams) ? bv[1] : fminf(worst, score);

    // select this block's slot j from the sorted arrays (static-index select)
    int   ord_j = j;
    float bv_j  = 0.f;
#pragma unroll
    for (int i = 0; i < NSLOT; i++)
        if (i == j) { ord_j = oi[i]; bv_j = bv[i]; }

    const int  src     = cond ? ord_j : j;
    const bool use_hyp = cond && (ord_j == ins_idx);

    // ---- scalar outputs ----
    if (tid == 0) {
        float ob = cond ? bv_j : __ldg(&board_in[(size_t)b * NSLOT + j]);
        out[(size_t)2 * batch + (size_t)b * NSLOT + j] = ob;
        if (j == 0) {
            out[b]         = (float)(cond ? new_len : ln);
            out[batch + b] = cond ? new_worst : worst;
        }
    }

    // ---- items row copy: int4 in -> float4 out ----
    const size_t src_off = ((size_t)b * NSLOT + src) * gen_len;
    const size_t dst_off = (size_t)batch * (2 + NSLOT) +
                           ((size_t)b * NSLOT + j) * gen_len;
    const int4* src_row = reinterpret_cast<const int4*>(items_in + src_off);
    const int4* hyp_row = reinterpret_cast<const int4*>(hyp + (size_t)b * hyp_w);
    float4*     dst_row = reinterpret_cast<float4*>(out + dst_off);

    const int nvec = gen_len >> 2;
    const bool clen_vec4 = ((cur_len & 3) == 0);

    for (int v = tid; v < nvec; v += 128) {
        int4 a = __ldg(&src_row[v]);
        if (use_hyp) {
            int base = v << 2;
            if (base < cur_len) {
                if (clen_vec4) {
                    a = __ldg(&hyp_row[v]);          // whole vec inside hyp region
                } else {
                    const int* h = hyp + (size_t)b * hyp_w;
                    if (base + 0 < cur_len) a.x = h[base + 0];
                    if (base + 1 < cur_len) a.y = h[base + 1];
                    if (base + 2 < cur_len) a.z = h[base + 2];
                    if (base + 3 < cur_len) a.w = h[base + 3];
                }
            }
        }
        float4 f;
        f.x = (float)a.x; f.y = (float)a.y; f.z = (float)a.z; f.w = (float)a.w;
        dst_row[v] = f;
    }
}

extern "C" void kernel_launch(void* const* d_in, const int* in_sizes, int n_in,
                              void* d_out, int out_size)
{
    const int*   hyp      = (const int*)  d_in[0];
    const float* slp      = (const float*)d_in[1];
    const int*   lnst     = (const int*)  d_in[2];
    const float* worst    = (const float*)d_in[3];
    const float* board    = (const float*)d_in[4];
    const int*   items    = (const int*)  d_in[5];
    const int*   curlen   = (n_in > 6) ? (const int*)d_in[6] : nullptr;

    const int batch   = in_sizes[1];                       // 4096
    const int hyp_w   = in_sizes[0] / batch;               // 128
    const int gen_len = in_sizes[5] / (batch * NSLOT);     // 2048

    dim3 grid(NSLOT, batch);
    beam_update_kernel<<<grid, 128>>>(hyp, slp, lnst, worst, board, items,
                                      curlen, (float*)d_out,
                                      batch, hyp_w, gen_len);
}

// round 3
// speedup vs baseline: 1.0566x; 1.0566x over previous
#include <cuda_runtime.h>
#include <cstdint>

// Beam hypotheses update, split into:
//   (1) meta kernel: per-row 9-way stable argsort -> scalar outputs + per-slot
//       source codes in device scratch
//   (2) copy kernel: pure streaming permute-copy int32 -> float32
// Output (float32, concatenated): len[B], worst[B], board[B,9], items[B,9,G].

#define NSLOT 9
#define MAX_BJ (1 << 20)          // scratch capacity (rows * 9), 4 MB

__device__ int g_srccode[MAX_BJ]; // low 16 bits: src slot; bit 30: use_hyp

// ---------------------------------------------------------------- meta kernel
__global__ void beam_meta_kernel(
    const float* __restrict__ slp,
    const int*   __restrict__ lnst,
    const float* __restrict__ worst_in,
    const float* __restrict__ board_in,
    const int*   __restrict__ curlen_ptr,
    float*       __restrict__ out,
    int batch, int hyp_w)
{
    const int b = blockIdx.x * blockDim.x + threadIdx.x;
    if (b >= batch) return;

    const int cur_len   = curlen_ptr ? __ldg(curlen_ptr) : hyp_w;
    const int num_beams = NSLOT - 1;

    const float score = __ldg(&slp[b]) / (float)cur_len;   // length_penalty = 1
    const int   ln    = __ldg(&lnst[b]);
    const float worst = __ldg(&worst_in[b]);
    const bool  cond  = (ln < num_beams) || (score > worst);
    const int   new_len = ln + 1;
    const int   ins_idx = (new_len > NSLOT) ? 0 : num_beams;

    float bin[NSLOT], bv[NSLOT];
    int   oi[NSLOT];
#pragma unroll
    for (int i = 0; i < NSLOT; i++) {
        bin[i] = __ldg(&board_in[(size_t)b * NSLOT + i]);
        bv[i]  = (i == ins_idx) ? score : bin[i];
        oi[i]  = i;
    }

    // fully unrolled bubble sort on (value, original-index) == stable argsort
#pragma unroll
    for (int p = 0; p < NSLOT - 1; p++) {
#pragma unroll
        for (int k = 0; k < NSLOT - 1; k++) {
            if (k < NSLOT - 1 - p) {
                bool sw = (bv[k] > bv[k + 1]) ||
                          (bv[k] == bv[k + 1] && oi[k] > oi[k + 1]);
                if (sw) {
                    float tv = bv[k]; bv[k] = bv[k + 1]; bv[k + 1] = tv;
                    int   ti = oi[k]; oi[k] = oi[k + 1]; oi[k + 1] = ti;
                }
            }
        }
    }

    const float new_worst = (new_len > num_beams) ? bv[1] : fminf(worst, score);

    out[b]         = (float)(cond ? new_len : ln);
    out[batch + b] = cond ? new_worst : worst;

    float* ob = out + (size_t)2 * batch + (size_t)b * NSLOT;
    int*   sc = g_srccode + (size_t)b * NSLOT;
#pragma unroll
    for (int j = 0; j < NSLOT; j++) {
        ob[j] = cond ? bv[j] : bin[j];
        int src = cond ? oi[j] : j;
        int code = src | ((cond && oi[j] == ins_idx) ? 0x40000000 : 0);
        sc[j] = code;
    }
}

// ---------------------------------------------------------------- copy kernel
template <int VPT>
__global__ __launch_bounds__(128) void beam_copy_kernel(
    const int* __restrict__ hyp,        // [B, hyp_w]
    const int* __restrict__ items_in,   // [B, 9, G]
    const int* __restrict__ curlen_ptr,
    float*     __restrict__ out,
    int batch, int hyp_w, int gen_len)
{
    const int j   = blockIdx.x;
    const int b   = blockIdx.y;
    const int tid = threadIdx.x;

    const int code     = g_srccode[(size_t)b * NSLOT + j];
    const int src      = code & 0xFFFF;
    const bool use_hyp = (code & 0x40000000) != 0;
    const int cur_len  = curlen_ptr ? __ldg(curlen_ptr) : hyp_w;

    const size_t src_off = ((size_t)b * NSLOT + src) * gen_len;
    const size_t dst_off = (size_t)batch * (2 + NSLOT) +
                           ((size_t)b * NSLOT + j) * gen_len;
    const int4* src_row = reinterpret_cast<const int4*>(items_in + src_off);
    float4*     dst_row = reinterpret_cast<float4*>(out + dst_off);

    int4 a[VPT];
#pragma unroll
    for (int it = 0; it < VPT; it++)
        a[it] = __ldcs(&src_row[tid + it * 128]);

    if (use_hyp) {
        const int* h = hyp + (size_t)b * hyp_w;
        if ((cur_len & 3) == 0) {
            const int4* hyp_row = reinterpret_cast<const int4*>(h);
            const int cvec = cur_len >> 2;
#pragma unroll
            for (int it = 0; it < VPT; it++) {
                int v = tid + it * 128;
                if (v < cvec) a[it] = __ldg(&hyp_row[v]);
            }
        } else {
#pragma unroll
            for (int it = 0; it < VPT; it++) {
                int base = (tid + it * 128) << 2;
                if (base < cur_len) {
                    if (base + 0 < cur_len) a[it].x = h[base + 0];
                    if (base + 1 < cur_len) a[it].y = h[base + 1];
                    if (base + 2 < cur_len) a[it].z = h[base + 2];
                    if (base + 3 < cur_len) a[it].w = h[base + 3];
                }
            }
        }
    }

#pragma unroll
    for (int it = 0; it < VPT; it++) {
        float4 f;
        f.x = (float)a[it].x; f.y = (float)a[it].y;
        f.z = (float)a[it].z; f.w = (float)a[it].w;
        __stcs(&dst_row[tid + it * 128], f);
    }
}

// generic fallback (arbitrary gen_len)
__global__ __launch_bounds__(128) void beam_copy_kernel_gen(
    const int* __restrict__ hyp,
    const int* __restrict__ items_in,
    const int* __restrict__ curlen_ptr,
    float*     __restrict__ out,
    int batch, int hyp_w, int gen_len)
{
    const int j   = blockIdx.x;
    const int b   = blockIdx.y;
    const int tid = threadIdx.x;

    const int code     = g_srccode[(size_t)b * NSLOT + j];
    const int src      = code & 0xFFFF;
    const bool use_hyp = (code & 0x40000000) != 0;
    const int cur_len  = curlen_ptr ? __ldg(curlen_ptr) : hyp_w;

    const int* src_row = items_in + ((size_t)b * NSLOT + src) * gen_len;
    float*     dst_row = out + (size_t)batch * (2 + NSLOT) +
                         ((size_t)b * NSLOT + j) * gen_len;
    const int* h = hyp + (size_t)b * hyp_w;

    for (int e = tid; e < gen_len; e += 128) {
        int v = (use_hyp && e < cur_len) ? h[e] : __ldcs(&src_row[e]);
        __stcs(&dst_row[e], (float)v);
    }
}

extern "C" void kernel_launch(void* const* d_in, const int* in_sizes, int n_in,
                              void* d_out, int out_size)
{
    const int*   hyp    = (const int*)  d_in[0];
    const float* slp    = (const float*)d_in[1];
    const int*   lnst   = (const int*)  d_in[2];
    const float* worst  = (const float*)d_in[3];
    const float* board  = (const float*)d_in[4];
    const int*   items  = (const int*)  d_in[5];
    const int*   curlen = (n_in > 6) ? (const int*)d_in[6] : nullptr;

    const int batch   = in_sizes[1];
    const int hyp_w   = in_sizes[0] / batch;
    const int gen_len = in_sizes[5] / (batch * NSLOT);
    float* out = (float*)d_out;

    beam_meta_kernel<<<(batch + 127) / 128, 128>>>(
        slp, lnst, worst, board, curlen, out, batch, hyp_w);

    dim3 grid(NSLOT, batch);
    if (gen_len == 2048) {
        beam_copy_kernel<4><<<grid, 128>>>(hyp, items, curlen, out,
                                           batch, hyp_w, gen_len);
    } else {
        beam_copy_kernel_gen<<<grid, 128>>>(hyp, items, curlen, out,
                                            batch, hyp_w, gen_len);
    }
}

// round 4
// speedup vs baseline: 1.1026x; 1.0435x over previous
#include <cuda_runtime.h>
#include <cstdint>

// Beam hypotheses update — single fused kernel.
// Block (j, b): warp 0 redundantly computes the per-row 9-way stable argsort,
// publishes this block's source-slot code via shared memory; all warps then do
// a front-batched streaming permute-copy of one 2048-int row (int32 -> fp32).
// Output (float32, concatenated): len[B], worst[B], board[B,9], items[B,9,G].

#define NSLOT 9

template <int VPT>
__global__ __launch_bounds__(128) void beam_fused_kernel(
    const int*   __restrict__ hyp,        // [B, hyp_w]
    const float* __restrict__ slp,        // [B]
    const int*   __restrict__ lnst,       // [B]
    const float* __restrict__ worst_in,   // [B]
    const float* __restrict__ board_in,   // [B, 9]
    const int*   __restrict__ items_in,   // [B, 9, G]
    const int*   __restrict__ curlen_ptr, // scalar (may be null)
    float*       __restrict__ out,
    int batch, int hyp_w, int gen_len)
{
    const int j   = blockIdx.x;           // output slot 0..8
    const int b   = blockIdx.y;           // batch row
    const int tid = threadIdx.x;

    __shared__ int s_code;                // low bits: src slot; bit30: use_hyp

    const int cur_len = curlen_ptr ? __ldg(curlen_ptr) : hyp_w;

    if (tid < 32) {                       // warp 0: redundant per-lane meta
        const int num_beams = NSLOT - 1;
        const float score = __ldg(&slp[b]) / (float)cur_len;  // len_pen = 1
        const int   ln    = __ldg(&lnst[b]);
        const float worst = __ldg(&worst_in[b]);
        const bool  cond  = (ln < num_beams) || (score > worst);
        const int   new_len = ln + 1;
        const int   ins_idx = (new_len > NSLOT) ? 0 : num_beams;

        float bin[NSLOT], bv[NSLOT];
        int   oi[NSLOT];
#pragma unroll
        for (int i = 0; i < NSLOT; i++) {
            bin[i] = __ldg(&board_in[(size_t)b * NSLOT + i]);
            bv[i]  = (i == ins_idx) ? score : bin[i];
            oi[i]  = i;
        }
        // fully unrolled bubble sort on (value, idx) == stable argsort
#pragma unroll
        for (int p = 0; p < NSLOT - 1; p++) {
#pragma unroll
            for (int k = 0; k < NSLOT - 1; k++) {
                if (k < NSLOT - 1 - p) {
                    bool sw = (bv[k] > bv[k + 1]) ||
                              (bv[k] == bv[k + 1] && oi[k] > oi[k + 1]);
                    if (sw) {
                        float tv = bv[k]; bv[k] = bv[k + 1]; bv[k + 1] = tv;
                        int   ti = oi[k]; oi[k] = oi[k + 1]; oi[k + 1] = ti;
                    }
                }
            }
        }

        int   ord_j = j;
        float bv_j  = 0.f, bin_j = 0.f;
#pragma unroll
        for (int i = 0; i < NSLOT; i++)
            if (i == j) { ord_j = oi[i]; bv_j = bv[i]; bin_j = bin[i]; }

        if (tid == 0) {
            int src = cond ? ord_j : j;
            s_code = src | ((cond && ord_j == ins_idx) ? 0x40000000 : 0);

            out[(size_t)2 * batch + (size_t)b * NSLOT + j] =
                cond ? bv_j : bin_j;
            if (j == 0) {
                const float new_worst =
                    (new_len > num_beams) ? bv[1] : fminf(worst, score);
                out[b]         = (float)(cond ? new_len : ln);
                out[batch + b] = cond ? new_worst : worst;
            }
        }
    }
    __syncthreads();

    const int  code    = s_code;
    const int  src     = code & 0xFFFF;
    const bool use_hyp = (code & 0x40000000) != 0;

    const size_t src_off = ((size_t)b * NSLOT + src) * gen_len;
    const size_t dst_off = (size_t)batch * (2 + NSLOT) +
                           ((size_t)b * NSLOT + j) * gen_len;
    const int4* src_row = reinterpret_cast<const int4*>(items_in + src_off);
    float4*     dst_row = reinterpret_cast<float4*>(out + dst_off);

    int4 a[VPT];
#pragma unroll
    for (int it = 0; it < VPT; it++)
        a[it] = __ldcs(&src_row[tid + it * 128]);

    if (use_hyp) {
        const int* h = hyp + (size_t)b * hyp_w;
        if ((cur_len & 3) == 0 && (hyp_w & 3) == 0) {
            const int4* hyp_row = reinterpret_cast<const int4*>(h);
            const int cvec = cur_len >> 2;
#pragma unroll
            for (int it = 0; it < VPT; it++) {
                int v = tid + it * 128;
                if (v < cvec) a[it] = __ldg(&hyp_row[v]);
            }
        } else {
#pragma unroll
            for (int it = 0; it < VPT; it++) {
                int base = (tid + it * 128) << 2;
                if (base + 0 < cur_len) a[it].x = h[base + 0];
                if (base + 1 < cur_len) a[it].y = h[base + 1];
                if (base + 2 < cur_len) a[it].z = h[base + 2];
                if (base + 3 < cur_len) a[it].w = h[base + 3];
            }
        }
    }

#pragma unroll
    for (int it = 0; it < VPT; it++) {
        float4 f;
        f.x = (float)a[it].x; f.y = (float)a[it].y;
        f.z = (float)a[it].z; f.w = (float)a[it].w;
        __stcs(&dst_row[tid + it * 128], f);
    }
}

// generic fallback for arbitrary gen_len
__global__ __launch_bounds__(128) void beam_fused_kernel_gen(
    const int*   __restrict__ hyp,
    const float* __restrict__ slp,
    const int*   __restrict__ lnst,
    const float* __restrict__ worst_in,
    const float* __restrict__ board_in,
    const int*   __restrict__ items_in,
    const int*   __restrict__ curlen_ptr,
    float*       __restrict__ out,
    int batch, int hyp_w, int gen_len)
{
    const int j   = blockIdx.x;
    const int b   = blockIdx.y;
    const int tid = threadIdx.x;

    __shared__ int s_code;
    const int cur_len = curlen_ptr ? __ldg(curlen_ptr) : hyp_w;

    if (tid < 32) {
        const int num_beams = NSLOT - 1;
        const float score = __ldg(&slp[b]) / (float)cur_len;
        const int   ln    = __ldg(&lnst[b]);
        const float worst = __ldg(&worst_in[b]);
        const bool  cond  = (ln < num_beams) || (score > worst);
        const int   new_len = ln + 1;
        const int   ins_idx = (new_len > NSLOT) ? 0 : num_beams;

        float bin[NSLOT], bv[NSLOT];
        int   oi[NSLOT];
#pragma unroll
        for (int i = 0; i < NSLOT; i++) {
            bin[i] = __ldg(&board_in[(size_t)b * NSLOT + i]);
            bv[i]  = (i == ins_idx) ? score : bin[i];
            oi[i]  = i;
        }
#pragma unroll
        for (int p = 0; p < NSLOT - 1; p++) {
#pragma unroll
            for (int k = 0; k < NSLOT - 1; k++) {
                if (k < NSLOT - 1 - p) {
                    bool sw = (bv[k] > bv[k + 1]) ||
                              (bv[k] == bv[k + 1] && oi[k] > oi[k + 1]);
                    if (sw) {
                        float tv = bv[k]; bv[k] = bv[k + 1]; bv[k + 1] = tv;
                        int   ti = oi[k]; oi[k] = oi[k + 1]; oi[k + 1] = ti;
                    }
                }
            }
        }

        int   ord_j = j;
        float bv_j  = 0.f, bin_j = 0.f;
#pragma unroll
        for (int i = 0; i < NSLOT; i++)
            if (i == j) { ord_j = oi[i]; bv_j = bv[i]; bin_j = bin[i]; }

        if (tid == 0) {
            int src = cond ? ord_j : j;
            s_code = src | ((cond && ord_j == ins_idx) ? 0x40000000 : 0);
            out[(size_t)2 * batch + (size_t)b * NSLOT + j] =
                cond ? bv_j : bin_j;
            if (j == 0) {
                const float new_worst =
                    (new_len > num_beams) ? bv[1] : fminf(worst, score);
                out[b]         = (float)(cond ? new_len : ln);
                out[batch + b] = cond ? new_worst : worst;
            }
        }
    }
    __syncthreads();

    const int  code    = s_code;
    const int  src     = code & 0xFFFF;
    const bool use_hyp = (code & 0x40000000) != 0;

    const int* src_row = items_in + ((size_t)b * NSLOT + src) * gen_len;
    float*     dst_row = out + (size_t)batch * (2 + NSLOT) +
                         ((size_t)b * NSLOT + j) * gen_len;
    const int* h = hyp + (size_t)b * hyp_w;

    for (int e = tid; e < gen_len; e += 128) {
        int v = (use_hyp && e < cur_len) ? h[e] : __ldcs(&src_row[e]);
        __stcs(&dst_row[e], (float)v);
    }
}

extern "C" void kernel_launch(void* const* d_in, const int* in_sizes, int n_in,
                              void* d_out, int out_size)
{
    const int*   hyp    = (const int*)  d_in[0];
    const float* slp    = (const float*)d_in[1];
    const int*   lnst   = (const int*)  d_in[2];
    const float* worst  = (const float*)d_in[3];
    const float* board  = (const float*)d_in[4];
    const int*   items  = (const int*)  d_in[5];
    const int*   curlen = (n_in > 6) ? (const int*)d_in[6] : nullptr;

    const int batch   = in_sizes[1];
    const int hyp_w   = in_sizes[0] / batch;
    const int gen_len = in_sizes[5] / (batch * NSLOT);
    float* out = (float*)d_out;

    dim3 grid(NSLOT, batch);
    if (gen_len == 2048) {
        beam_fused_kernel<4><<<grid, 128>>>(
            hyp, slp, lnst, worst, board, items, curlen, out,
            batch, hyp_w, gen_len);
    } else {
        beam_fused_kernel_gen<<<grid, 128>>>(
            hyp, slp, lnst, worst, board, items, curlen, out,
            batch, hyp_w, gen_len);
    }
}

// round 5
// speedup vs baseline: 1.1105x; 1.0072x over previous
#include <cuda_runtime.h>
#include <cstdint>

// Beam hypotheses update — single fused SCATTER kernel.
// Block (j, b) reads items row j (address known at cycle 0 -> loads front-issued,
// overlapped with meta), computes the rank of slot j in the post-insert board,
// and scatters the row (int32 -> fp32) to its destination rank. No smem, no
// barrier. Output (f32, concat): len[B], worst[B], board[B,9], items[B,9,G].

#define NSLOT 9

template <int VPT>
__global__ __launch_bounds__(128) void beam_scatter_kernel(
    const int*   __restrict__ hyp,        // [B, hyp_w]
    const float* __restrict__ slp,        // [B]
    const int*   __restrict__ lnst,       // [B]
    const float* __restrict__ worst_in,   // [B]
    const float* __restrict__ board_in,   // [B, 9]
    const int*   __restrict__ items_in,   // [B, 9, G]
    const int*   __restrict__ curlen_ptr, // scalar (may be null)
    float*       __restrict__ out,
    int batch, int hyp_w, int gen_len)
{
    const int j   = blockIdx.x;           // SOURCE slot 0..8
    const int b   = blockIdx.y;           // batch row
    const int tid = threadIdx.x;

    // ---- front-batched source loads: address independent of meta ----
    const int4* src_row = reinterpret_cast<const int4*>(
        items_in + ((size_t)b * NSLOT + j) * gen_len);
    int4 a[VPT];
#pragma unroll
    for (int it = 0; it < VPT; it++)
        a[it] = __ldcs(&src_row[tid + it * 128]);

    // ---- meta (redundant per thread; no sort, rank-select only) ----
    const int cur_len   = curlen_ptr ? __ldg(curlen_ptr) : hyp_w;
    const int num_beams = NSLOT - 1;

    const float score = __ldg(&slp[b]) / (float)cur_len;   // length_penalty=1
    const int   ln    = __ldg(&lnst[b]);
    const float worst = __ldg(&worst_in[b]);
    const bool  cond  = (ln < num_beams) || (score > worst);
    const int   new_len = ln + 1;
    const int   ins_idx = (new_len > NSLOT) ? 0 : num_beams;

    float v[NSLOT];
    float binj = 0.f;
#pragma unroll
    for (int i = 0; i < NSLOT; i++) {
        v[i] = __ldg(&board_in[(size_t)b * NSLOT + i]);
        if (i == j) binj = v[i];
    }
#pragma unroll
    for (int i = 0; i < NSLOT; i++)
        if (i == ins_idx) v[i] = score;

    // rank of element j under stable (value, index) ascending order
    int r = 0;
#pragma unroll
    for (int k = 0; k < NSLOT; k++)
        if (k != j)
            r += ((v[k] < v[j]) || (v[k] == v[j] && k < j)) ? 1 : 0;

    const int  dest    = cond ? r : j;
    const bool use_hyp = cond && (j == ins_idx);

    // ---- scalar outputs ----
    if (tid == 0) {
        out[(size_t)2 * batch + (size_t)b * NSLOT + dest] = cond ? v[j] : binj;
        if (j == 0) {
            // second smallest by (value, index)
            float m1 = v[0]; int m1i = 0;
#pragma unroll
            for (int i = 1; i < NSLOT; i++)
                if (v[i] < m1) { m1 = v[i]; m1i = i; }
            float m2 = 3.402823466e+38f;
#pragma unroll
            for (int i = 0; i < NSLOT; i++)
                if (i != m1i) m2 = fminf(m2, v[i]);
            const float new_worst =
                (new_len > num_beams) ? m2 : fminf(worst, score);
            out[b]         = (float)(cond ? new_len : ln);
            out[batch + b] = cond ? new_worst : worst;
        }
    }

    // ---- hyp overlay (only the replaced source row; first cur_len elems) ----
    if (use_hyp) {
        const int* h = hyp + (size_t)b * hyp_w;
        if ((cur_len & 3) == 0 && (hyp_w & 3) == 0) {
            const int4* hyp_row = reinterpret_cast<const int4*>(h);
            const int cvec = cur_len >> 2;
#pragma unroll
            for (int it = 0; it < VPT; it++) {
                int vix = tid + it * 128;
                if (vix < cvec) a[it] = __ldg(&hyp_row[vix]);
            }
        } else {
#pragma unroll
            for (int it = 0; it < VPT; it++) {
                int base = (tid + it * 128) << 2;
                if (base + 0 < cur_len) a[it].x = h[base + 0];
                if (base + 1 < cur_len) a[it].y = h[base + 1];
                if (base + 2 < cur_len) a[it].z = h[base + 2];
                if (base + 3 < cur_len) a[it].w = h[base + 3];
            }
        }
    }

    // ---- scatter stores ----
    float4* dst_row = reinterpret_cast<float4*>(
        out + (size_t)batch * (2 + NSLOT) +
        ((size_t)b * NSLOT + dest) * gen_len);
#pragma unroll
    for (int it = 0; it < VPT; it++) {
        float4 f;
        f.x = (float)a[it].x; f.y = (float)a[it].y;
        f.z = (float)a[it].z; f.w = (float)a[it].w;
        __stcs(&dst_row[tid + it * 128], f);
    }
}

// generic fallback for arbitrary gen_len (same scatter logic, scalar loop)
__global__ __launch_bounds__(128) void beam_scatter_kernel_gen(
    const int*   __restrict__ hyp,
    const float* __restrict__ slp,
    const int*   __restrict__ lnst,
    const float* __restrict__ worst_in,
    const float* __restrict__ board_in,
    const int*   __restrict__ items_in,
    const int*   __restrict__ curlen_ptr,
    float*       __restrict__ out,
    int batch, int hyp_w, int gen_len)
{
    const int j   = blockIdx.x;
    const int b   = blockIdx.y;
    const int tid = threadIdx.x;

    const int cur_len   = curlen_ptr ? __ldg(curlen_ptr) : hyp_w;
    const int num_beams = NSLOT - 1;

    const float score = __ldg(&slp[b]) / (float)cur_len;
    const int   ln    = __ldg(&lnst[b]);
    const float worst = __ldg(&worst_in[b]);
    const bool  cond  = (ln < num_beams) || (score > worst);
    const int   new_len = ln + 1;
    const int   ins_idx = (new_len > NSLOT) ? 0 : num_beams;

    float v[NSLOT];
    float binj = 0.f;
#pragma unroll
    for (int i = 0; i < NSLOT; i++) {
        v[i] = __ldg(&board_in[(size_t)b * NSLOT + i]);
        if (i == j) binj = v[i];
    }
#pragma unroll
    for (int i = 0; i < NSLOT; i++)
        if (i == ins_idx) v[i] = score;

    int r = 0;
#pragma unroll
    for (int k = 0; k < NSLOT; k++)
        if (k != j)
            r += ((v[k] < v[j]) || (v[k] == v[j] && k < j)) ? 1 : 0;

    const int  dest    = cond ? r : j;
    const bool use_hyp = cond && (j == ins_idx);

    if (tid == 0) {
        out[(size_t)2 * batch + (size_t)b * NSLOT + dest] = cond ? v[j] : binj;
        if (j == 0) {
            float m1 = v[0]; int m1i = 0;
#pragma unroll
            for (int i = 1; i < NSLOT; i++)
                if (v[i] < m1) { m1 = v[i]; m1i = i; }
            float m2 = 3.402823466e+38f;
#pragma unroll
            for (int i = 0; i < NSLOT; i++)
                if (i != m1i) m2 = fminf(m2, v[i]);
            const float new_worst =
                (new_len > num_beams) ? m2 : fminf(worst, score);
            out[b]         = (float)(cond ? new_len : ln);
            out[batch + b] = cond ? new_worst : worst;
        }
    }

    const int* src_row = items_in + ((size_t)b * NSLOT + j) * gen_len;
    float*     dst_row = out + (size_t)batch * (2 + NSLOT) +
                         ((size_t)b * NSLOT + dest) * gen_len;
    const int* h = hyp + (size_t)b * hyp_w;

    for (int e = tid; e < gen_len; e += 128) {
        int val = (use_hyp && e < cur_len) ? h[e] : __ldcs(&src_row[e]);
        __stcs(&dst_row[e], (float)val);
    }
}

extern "C" void kernel_launch(void* const* d_in, const int* in_sizes, int n_in,
                              void* d_out, int out_size)
{
    const int*   hyp    = (const int*)  d_in[0];
    const float* slp    = (const float*)d_in[1];
    const int*   lnst   = (const int*)  d_in[2];
    const float* worst  = (const float*)d_in[3];
    const float* board  = (const float*)d_in[4];
    const int*   items  = (const int*)  d_in[5];
    const int*   curlen = (n_in > 6) ? (const int*)d_in[6] : nullptr;

    const int batch   = in_sizes[1];
    const int hyp_w   = in_sizes[0] / batch;
    const int gen_len = in_sizes[5] / (batch * NSLOT);
    float* out = (float*)d_out;

    dim3 grid(NSLOT, batch);
    if (gen_len == 2048) {
        beam_scatter_kernel<4><<<grid, 128>>>(
            hyp, slp, lnst, worst, board, items, curlen, out,
            batch, hyp_w, gen_len);
    } else {
        beam_scatter_kernel_gen<<<grid, 128>>>(
            hyp, slp, lnst, worst, board, items, curlen, out,
            batch, hyp_w, gen_len);
    }
}